// round 4
// baseline (speedup 1.0000x reference)
#include <cuda_runtime.h>
#include <cuda_fp16.h>
#include <cstdint>

#define BSZ 256   // batch
#define SS  512   // seq
#define II  128   // in features
#define OO  128   // out features
#define LLG 11    // lags (MAX_LAG+1)
#define HH  16    // modulator hidden
#define HP  8     // half2 pairs (HH/2)
#define YCH 7     // batch chunks (4x37 + 3x36 = 256)

__device__ float g_xm[BSZ * II];   // mean over S, [b][i]

__device__ __forceinline__ float tanh_fast(float x) {
    float y;
    asm("tanh.approx.f32 %0, %1;" : "=f"(y) : "f"(x));
    return y;
}
__device__ __forceinline__ __half2 tanh2_fast(__half2 x) {
    unsigned xi = *reinterpret_cast<unsigned*>(&x), yi;
    asm("tanh.approx.f16x2 %0, %1;" : "=r"(yi) : "r"(xi));
    return *reinterpret_cast<__half2*>(&yi);
}
// sigmoid(x) = 0.5*tanh(x/2) + 0.5   (single MUFU)
__device__ __forceinline__ float sigmoid_t(float x) {
    return fmaf(tanh_fast(0.5f * x), 0.5f, 0.5f);
}

// ---------------------------------------------------------------------------
// Kernel 1: xm[b][i] = mean_s x[b][s][i]; also zeroes out[b][:] for RED.ADD.
// ---------------------------------------------------------------------------
__global__ __launch_bounds__(512) void xm_kernel(const float* __restrict__ x,
                                                 float* __restrict__ out) {
    int b = blockIdx.x;
    int i = threadIdx.x & 127;
    int c = threadIdx.x >> 7;   // 0..3
    if (threadIdx.x < OO) out[(size_t)b * OO + threadIdx.x] = 0.0f;
    const float* p = x + (size_t)b * SS * II + (size_t)c * 128 * II + i;
    float s = 0.0f;
#pragma unroll 8
    for (int j = 0; j < 128; j++) s += p[(size_t)j * II];
    __shared__ float red[4][128];
    red[c][i] = s;
    __syncthreads();
    if (c == 0)
        g_xm[b * II + i] = (red[0][i] + red[1][i] + red[2][i] + red[3][i]) * (1.0f / SS);
}

// ---------------------------------------------------------------------------
// Per-(o,i) parameters held in registers across the batch loop.
// ---------------------------------------------------------------------------
struct P {
    float   wl[LLG];
    float   C[5];
    __half2 W12[HP], B12[HP], W22[HP];
    float   b2v;
};

__device__ __forceinline__ float triple(const float* __restrict__ hp,
                                        float xmv, const P& p) {
    // front-batched lag loads (high MLP)
    float hv[LLG];
#pragma unroll
    for (int l = 0; l < LLG; l++) hv[l] = hp[-(l * II)];

    // lagged input
    float xl = 0.0f;
#pragma unroll
    for (int l = 0; l < LLG; l++) xl = fmaf(hv[l], p.wl[l], xl);

    // spline lookup + lerp (s*4 < 4 -> knots 0..3)
    float s   = sigmoid_t(xl);
    float idx = s * 4.0f;
    int   k   = (int)idx;
    k = (k > 3) ? 3 : k;
    float w1f = idx - (float)k;
    float c0 = (k == 0) ? p.C[0] : (k == 1) ? p.C[1] : (k == 2) ? p.C[2] : p.C[3];
    float c1 = (k == 0) ? p.C[1] : (k == 1) ? p.C[2] : (k == 2) ? p.C[3] : p.C[4];
    float y  = fmaf(c1 - c0, w1f, c0);

    // modulator MLP in f16x2: 8 HFMA2 + 8 tanh.f16x2 + 8 HFMA2
    __half2 xm2 = __float2half2_rn(xmv);
    __half2 a0 = __float2half2_rn(0.0f), a1 = a0;
#pragma unroll
    for (int h = 0; h < HP; h += 2) {
        __half2 t0 = tanh2_fast(__hfma2(xm2, p.W12[h],     p.B12[h]));
        __half2 t1 = tanh2_fast(__hfma2(xm2, p.W12[h + 1], p.B12[h + 1]));
        a0 = __hfma2(t0, p.W22[h],     a0);
        a1 = __hfma2(t1, p.W22[h + 1], a1);
    }
    float2 f0 = __half22float2(a0);
    float2 f1 = __half22float2(a1);
    float acc = p.b2v + (f0.x + f0.y) + (f1.x + f1.y);
    float alpha = sigmoid_t(acc);
    return y * alpha;
}

// ---------------------------------------------------------------------------
// Kernel 2: main.  grid=(64, 7), block=256 = 2 o-rows x 128 i, occ target 3
// -> 448 blocks vs 444 resident = 1.01 waves.  UF=2 batch ILP, warp shfl
// reduce, RED.E.ADD accumulation, no smem/syncthreads.
// ---------------------------------------------------------------------------
__global__ __launch_bounds__(256, 3) void main_kernel(
    const float* __restrict__ x,
    const float* __restrict__ coeffs,
    const float* __restrict__ lag_logits,
    const float* __restrict__ mw1,
    const float* __restrict__ mb1,
    const float* __restrict__ mw2,
    const float* __restrict__ mb2,
    const float* __restrict__ edge,
    float* __restrict__ out)
{
    int tid = threadIdx.x;
    int i  = tid & 127;
    int ol = tid >> 7;                 // 0 or 1
    int o  = blockIdx.x * 2 + ol;
    int oi = o * II + i;

    int y  = blockIdx.y;
    int bs = (y < 4) ? y * 37 : 148 + (y - 4) * 36;
    int be = bs + ((y < 4) ? 37 : 36);

    P p;
    // softmax over lag logits
    float m = -1e30f;
#pragma unroll
    for (int l = 0; l < LLG; l++) { p.wl[l] = lag_logits[oi * LLG + l]; m = fmaxf(m, p.wl[l]); }
    float sum = 0.0f;
#pragma unroll
    for (int l = 0; l < LLG; l++) { p.wl[l] = __expf(p.wl[l] - m); sum += p.wl[l]; }
    float inv = __fdividef(1.0f, sum);
#pragma unroll
    for (int l = 0; l < LLG; l++) p.wl[l] *= inv;

    // edge mask folded into coefficients
    float mask = (edge[oi] > 0.0f) ? 1.0f : 0.0f;
#pragma unroll
    for (int j = 0; j < 5; j++) p.C[j] = coeffs[oi * 8 + j] * mask;

#pragma unroll
    for (int h = 0; h < HP; h++) {
        p.W12[h] = __floats2half2_rn(mw1[oi * HH + 2 * h], mw1[oi * HH + 2 * h + 1]);
        p.B12[h] = __floats2half2_rn(mb1[oi * HH + 2 * h], mb1[oi * HH + 2 * h + 1]);
        p.W22[h] = __floats2half2_rn(mw2[oi * HH + 2 * h], mw2[oi * HH + 2 * h + 1]);
    }
    p.b2v = mb2[oi];

    const float* xb  = x + (size_t)(SS - 1) * II + i;   // x[b][S-1][i] base
    const float* xmp = g_xm + i;
    float* outp = out + o;

    int b = bs;
    for (; b + 1 < be; b += 2) {
        float v0 = triple(xb + (size_t)b       * SS * II, xmp[(size_t)b       * II], p);
        float v1 = triple(xb + (size_t)(b + 1) * SS * II, xmp[(size_t)(b + 1) * II], p);
#pragma unroll
        for (int off = 16; off; off >>= 1) {
            v0 += __shfl_xor_sync(0xffffffffu, v0, off);
            v1 += __shfl_xor_sync(0xffffffffu, v1, off);
        }
        if ((tid & 31) == 0) {
            atomicAdd(outp + (size_t)b       * OO, v0);
            atomicAdd(outp + (size_t)(b + 1) * OO, v1);
        }
    }
    if (b < be) {
        float v0 = triple(xb + (size_t)b * SS * II, xmp[(size_t)b * II], p);
#pragma unroll
        for (int off = 16; off; off >>= 1)
            v0 += __shfl_xor_sync(0xffffffffu, v0, off);
        if ((tid & 31) == 0)
            atomicAdd(outp + (size_t)b * OO, v0);
    }
}

extern "C" void kernel_launch(void* const* d_in, const int* in_sizes, int n_in,
                              void* d_out, int out_size) {
    const float* x      = (const float*)d_in[0];
    const float* coeffs = (const float*)d_in[1];
    const float* lag    = (const float*)d_in[2];
    const float* mw1    = (const float*)d_in[3];
    const float* mb1    = (const float*)d_in[4];
    const float* mw2    = (const float*)d_in[5];
    const float* mb2    = (const float*)d_in[6];
    const float* edge   = (const float*)d_in[7];
    float* out = (float*)d_out;

    xm_kernel<<<BSZ, 512>>>(x, out);
    dim3 grid(OO / 2, YCH);
    main_kernel<<<grid, 256>>>(x, coeffs, lag, mw1, mb1, mw2, mb2, edge, out);
}

// round 7
// speedup vs baseline: 1.4446x; 1.4446x over previous
#include <cuda_runtime.h>
#include <cuda_fp16.h>
#include <cstdint>

#define BSZ 256   // batch
#define SS  512   // seq
#define II  128   // in features
#define OO  128   // out features
#define LLG 11    // lags (MAX_LAG+1)
#define HH  16    // modulator hidden
#define HP  8     // half2 pairs (HH/2)
#define BPC 32    // batches per block chunk
#define BCH 8     // batch chunks (BPC*BCH == BSZ)
#define UF  4     // batches per inner iteration (ILP)

__device__ float g_xm[BSZ * II];   // mean over S, [b][i]

__device__ __forceinline__ float tanh_fast(float x) {
    float y;
    asm("tanh.approx.f32 %0, %1;" : "=f"(y) : "f"(x));
    return y;
}
__device__ __forceinline__ __half2 tanh2_fast(__half2 x) {
    unsigned xi = *reinterpret_cast<unsigned*>(&x), yi;
    asm("tanh.approx.f16x2 %0, %1;" : "=r"(yi) : "r"(xi));
    return *reinterpret_cast<__half2*>(&yi);
}
// sigmoid(x) = 0.5*tanh(x/2) + 0.5   (single MUFU)
__device__ __forceinline__ float sigmoid_t(float x) {
    return fmaf(tanh_fast(0.5f * x), 0.5f, 0.5f);
}

// ---------------------------------------------------------------------------
// Kernel 1: xm[b][i] = mean_s x[b][s][i]; also zeroes out[b][:] for RED.ADD.
// ---------------------------------------------------------------------------
__global__ __launch_bounds__(512) void xm_kernel(const float* __restrict__ x,
                                                 float* __restrict__ out) {
    int b = blockIdx.x;
    int i = threadIdx.x & 127;
    int c = threadIdx.x >> 7;   // 0..3
    if (threadIdx.x < OO) out[(size_t)b * OO + threadIdx.x] = 0.0f;
    const float* p = x + (size_t)b * SS * II + (size_t)c * 128 * II + i;
    float s = 0.0f;
#pragma unroll 8
    for (int j = 0; j < 128; j++) s += p[(size_t)j * II];
    __shared__ float red[4][128];
    red[c][i] = s;
    __syncthreads();
    if (c == 0)
        g_xm[b * II + i] = (red[0][i] + red[1][i] + red[2][i] + red[3][i]) * (1.0f / SS);
}

// ---------------------------------------------------------------------------
// Per-(o,i) parameters in registers; MLP weights packed half2 (~41 regs).
// ---------------------------------------------------------------------------
struct P {
    float   wl[LLG];
    float   C[5];
    __half2 W12[HP], B12[HP], W22[HP];
    float   b2v;
};

__device__ __forceinline__ float triple(const float* __restrict__ hp,
                                        float xmv, const P& p) {
    // lagged input, 2 accumulators to halve the dependency chain
    float xla = 0.0f, xlb = 0.0f;
#pragma unroll
    for (int l = 0; l < LLG - 1; l += 2) {
        xla = fmaf(hp[-(l * II)],       p.wl[l],     xla);
        xlb = fmaf(hp[-((l + 1) * II)], p.wl[l + 1], xlb);
    }
    xla = fmaf(hp[-((LLG - 1) * II)], p.wl[LLG - 1], xla);
    float xl = xla + xlb;

    // spline lookup + lerp (s*4 < 4 -> knots 0..3)
    float s   = sigmoid_t(xl);
    float idx = s * 4.0f;
    int   k   = (int)idx;
    k = (k > 3) ? 3 : k;
    float w1f = idx - (float)k;
    float c0 = (k == 0) ? p.C[0] : (k == 1) ? p.C[1] : (k == 2) ? p.C[2] : p.C[3];
    float c1 = (k == 0) ? p.C[1] : (k == 1) ? p.C[2] : (k == 2) ? p.C[3] : p.C[4];
    float y  = fmaf(c1 - c0, w1f, c0);

    // modulator MLP in f16x2: 8 HFMA2 + 8 tanh.f16x2 + 8 HFMA2
    __half2 xm2 = __float2half2_rn(xmv);
    __half2 a0 = __float2half2_rn(0.0f), a1 = a0;
#pragma unroll
    for (int h = 0; h < HP; h += 2) {
        __half2 t0 = tanh2_fast(__hfma2(xm2, p.W12[h],     p.B12[h]));
        __half2 t1 = tanh2_fast(__hfma2(xm2, p.W12[h + 1], p.B12[h + 1]));
        a0 = __hfma2(t0, p.W22[h],     a0);
        a1 = __hfma2(t1, p.W22[h + 1], a1);
    }
    float2 f0 = __half22float2(a0);
    float2 f1 = __half22float2(a1);
    float acc = p.b2v + (f0.x + f0.y) + (f1.x + f1.y);
    float alpha = sigmoid_t(acc);
    return y * alpha;
}

// ---------------------------------------------------------------------------
// Kernel 2: main.  grid=(64, 8), block=256 = 2 o-rows x 128 i, occ 2 (proven
// no-spill config).  UF=4 batch ILP, warp shfl reduce, RED.E.ADD.
// ---------------------------------------------------------------------------
__global__ __launch_bounds__(256, 2) void main_kernel(
    const float* __restrict__ x,
    const float* __restrict__ coeffs,
    const float* __restrict__ lag_logits,
    const float* __restrict__ mw1,
    const float* __restrict__ mb1,
    const float* __restrict__ mw2,
    const float* __restrict__ mb2,
    const float* __restrict__ edge,
    float* __restrict__ out)
{
    int tid = threadIdx.x;
    int i  = tid & 127;
    int ol = tid >> 7;                 // 0 or 1
    int o  = blockIdx.x * 2 + ol;
    int oi = o * II + i;
    int b0 = blockIdx.y * BPC;

    P p;
    // softmax over lag logits (amortized over BPC batches)
    float m = -1e30f;
#pragma unroll
    for (int l = 0; l < LLG; l++) { p.wl[l] = lag_logits[oi * LLG + l]; m = fmaxf(m, p.wl[l]); }
    float sum = 0.0f;
#pragma unroll
    for (int l = 0; l < LLG; l++) { p.wl[l] = __expf(p.wl[l] - m); sum += p.wl[l]; }
    float inv = __fdividef(1.0f, sum);
#pragma unroll
    for (int l = 0; l < LLG; l++) p.wl[l] *= inv;

    // edge mask folded into coefficients; s*4 < 4 => only coeffs[0..4]
    float mask = (edge[oi] > 0.0f) ? 1.0f : 0.0f;
#pragma unroll
    for (int j = 0; j < 5; j++) p.C[j] = coeffs[oi * 8 + j] * mask;

#pragma unroll
    for (int h = 0; h < HP; h++) {
        p.W12[h] = __floats2half2_rn(mw1[oi * HH + 2 * h], mw1[oi * HH + 2 * h + 1]);
        p.B12[h] = __floats2half2_rn(mb1[oi * HH + 2 * h], mb1[oi * HH + 2 * h + 1]);
        p.W22[h] = __floats2half2_rn(mw2[oi * HH + 2 * h], mw2[oi * HH + 2 * h + 1]);
    }
    p.b2v = mb2[oi];

    const float* xb  = x + ((size_t)b0 * SS + (SS - 1)) * II + i;  // x[b0][S-1][i]
    const float* xmp = g_xm + (size_t)b0 * II + i;
    float* outp = out + (size_t)b0 * OO + o;

    for (int bb = 0; bb < BPC; bb += UF) {
        float v[UF];
#pragma unroll
        for (int u = 0; u < UF; u++)
            v[u] = triple(xb + (size_t)(bb + u) * SS * II, xmp[(bb + u) * II], p);

        // warp-level i-reduction, UF independent trees interleaved
#pragma unroll
        for (int off = 16; off; off >>= 1)
#pragma unroll
            for (int u = 0; u < UF; u++)
                v[u] += __shfl_xor_sync(0xffffffffu, v[u], off);

        if ((tid & 31) == 0) {
#pragma unroll
            for (int u = 0; u < UF; u++)
                atomicAdd(outp + (size_t)(bb + u) * OO, v[u]);   // -> RED.E.ADD
        }
    }
}

extern "C" void kernel_launch(void* const* d_in, const int* in_sizes, int n_in,
                              void* d_out, int out_size) {
    const float* x      = (const float*)d_in[0];
    const float* coeffs = (const float*)d_in[1];
    const float* lag    = (const float*)d_in[2];
    const float* mw1    = (const float*)d_in[3];
    const float* mb1    = (const float*)d_in[4];
    const float* mw2    = (const float*)d_in[5];
    const float* mb2    = (const float*)d_in[6];
    const float* edge   = (const float*)d_in[7];
    float* out = (float*)d_out;

    xm_kernel<<<BSZ, 512>>>(x, out);
    dim3 grid(OO / 2, BCH);
    main_kernel<<<grid, 256>>>(x, coeffs, lag, mw1, mb1, mw2, mb2, edge, out);
}